// round 6
// baseline (speedup 1.0000x reference)
#include <cuda_runtime.h>

#define T_OBS 8
#define T_PRE 12
#define BATCH 524288
#define INP 2
#define H 8
#define EMB 16

typedef unsigned long long u64;

// ---------------- packed f32x2 + fast activation helpers (sm_103a) ----------------
__device__ __forceinline__ u64 fma2(u64 a, u64 b, u64 c) {
    u64 d; asm("fma.rn.f32x2 %0, %1, %2, %3;" : "=l"(d) : "l"(a), "l"(b), "l"(c)); return d;
}
__device__ __forceinline__ u64 pack2(float lo, float hi) {
    u64 d; asm("mov.b64 %0, {%1, %2};" : "=l"(d) : "f"(lo), "f"(hi)); return d;
}
__device__ __forceinline__ void unpack2(u64 v, float& lo, float& hi) {
    asm("mov.b64 {%0, %1}, %2;" : "=f"(lo), "=f"(hi) : "l"(v));
}
__device__ __forceinline__ float tanh_ap(float x) {
    float y; asm("tanh.approx.f32 %0, %1;" : "=f"(y) : "f"(x)); return y;
}

// Folded, gate-paired, sigmoid-prescaled weights.
// Rows for gates i (0..7), f (8..15), o (24..31) are pre-scaled by 0.5 so that
// sigmoid(x) = 0.5 + 0.5*tanh(acc) directly (acc already = x/2). Gate g rows
// (16..23) unscaled.
// Layout g_W[phase][unit k][pair pr][12]:
//   [0]=A0 [1]=A1 [2]=b  [3..10]=whh[0..7]  [11]=pad
// each u64 = (lo = first gate of pair, hi = second gate).
// pair0 = (i,f) rows (k, 8+k); pair1 = (g,o) rows (16+k, 24+k).
__device__ float g_rows[2][32][11];
__device__ u64   g_W[2][H][2][12];

__global__ void prep_kernel(const float* __restrict__ W_in, const float* __restrict__ b_in,
                            const float* __restrict__ W_ih_obs, const float* __restrict__ W_hh_obs,
                            const float* __restrict__ b_ih_obs, const float* __restrict__ b_hh_obs,
                            const float* __restrict__ W_ih_pre, const float* __restrict__ W_hh_pre,
                            const float* __restrict__ b_ih_pre, const float* __restrict__ b_hh_pre) {
    int j = threadIdx.x;   // gate row 0..31
    int p = threadIdx.y;   // phase
    const float* W_ih = p ? W_ih_pre : W_ih_obs;
    const float* W_hh = p ? W_hh_pre : W_hh_obs;
    const float* b_ih = p ? b_ih_pre : b_ih_obs;
    const float* b_hh = p ? b_hh_pre : b_hh_obs;

    // fold embedding: A = W_ih @ W_in (32x2), b_tot = W_ih@b_in + b_ih + b_hh
    float a0 = 0.f, a1 = 0.f, bb = 0.f;
#pragma unroll
    for (int e = 0; e < EMB; e++) {
        float w = W_ih[j * EMB + e];
        a0 = fmaf(w, W_in[e * INP + 0], a0);
        a1 = fmaf(w, W_in[e * INP + 1], a1);
        bb = fmaf(w, b_in[e], bb);
    }
    bb += b_ih[j] + b_hh[j];

    // pre-scale sigmoid gates (i, f, o) by 0.5
    float s = (j < 16 || j >= 24) ? 0.5f : 1.0f;
    g_rows[p][j][0] = a0 * s;
    g_rows[p][j][1] = a1 * s;
    g_rows[p][j][2] = bb * s;
#pragma unroll
    for (int m = 0; m < H; m++)
        g_rows[p][j][3 + m] = W_hh[j * H + m] * s;

    __syncthreads();

    if (j < 16) {
        int k  = j % H;       // unit
        int pr = j / H;       // pair
        int rlo = pr ? (16 + k) : k;
        int rhi = pr ? (24 + k) : (8 + k);
#pragma unroll
        for (int m = 0; m < 11; m++)
            g_W[p][k][pr][m] = pack2(g_rows[p][rlo][m], g_rows[p][rhi][m]);
        g_W[p][k][pr][11] = 0ull;
    }
}

// One phase scan. Weights register-resident (loaded once). vald[i] = (h[j^i], h[j^i]).
template <int T>
__device__ __forceinline__ void lstm_scan(const float* __restrict__ xin, int e, int j,
                                          const u64* __restrict__ sWk,  // &sW[p][j][0][0]
                                          u64 vald[H], float& cc) {
    // load weights into registers, permuted so slot i pairs with vald[i]
    u64 wA0_0 = sWk[0],  wA1_0 = sWk[1],  wb_0 = sWk[2];
    u64 wA0_1 = sWk[12], wA1_1 = sWk[13], wb_1 = sWk[14];
    u64 wh0[H], wh1[H];
#pragma unroll
    for (int i = 0; i < H; i++) {
        wh0[i] = sWk[3 + (j ^ i)];
        wh1[i] = sWk[12 + 3 + (j ^ i)];
    }

    float2 xv = *(const float2*)(xin + (size_t)e * INP);
#pragma unroll 1
    for (int t = 0; t < T; t++) {
        u64 x0d = pack2(xv.x, xv.x);
        u64 x1d = pack2(xv.y, xv.y);
        if (t + 1 < T)
            xv = *(const float2*)(xin + ((size_t)(t + 1) * BATCH + e) * INP);

        u64 acc0 = fma2(wA1_0, x1d, fma2(wA0_0, x0d, wb_0));
        u64 acc1 = fma2(wA1_1, x1d, fma2(wA0_1, x0d, wb_1));
#pragma unroll
        for (int i = 0; i < H; i++) {
            acc0 = fma2(wh0[i], vald[i], acc0);
            acc1 = fma2(wh1[i], vald[i], acc1);
        }
        float gi, gf, gg, go;
        unpack2(acc0, gi, gf);
        unpack2(acc1, gg, go);
        float si = fmaf(0.5f, tanh_ap(gi), 0.5f);   // rows pre-scaled: acc = x/2
        float sf = fmaf(0.5f, tanh_ap(gf), 0.5f);
        float gv = tanh_ap(gg);
        float so = fmaf(0.5f, tanh_ap(go), 0.5f);
        cc = fmaf(sf, cc, si * gv);
        float hv = so * tanh_ap(cc);

        // exchange: vald[i] = h of unit (j^i); 7 independent shuffles
        vald[0] = pack2(hv, hv);
#pragma unroll
        for (int i = 1; i < H; i++) {
            float v = __shfl_xor_sync(0xffffffffu, hv, i);
            vald[i] = pack2(v, v);
        }
    }
}

__global__ __launch_bounds__(256, 2) void lstm_kernel(
    const float* __restrict__ obs, const float* __restrict__ pre,
    const float* __restrict__ h0, const float* __restrict__ c0,
    const float* __restrict__ c0p, float* __restrict__ out)
{
    __shared__ u64 sW[2][H][2][12];
    {
        const u64* src = (const u64*)g_W;
        u64* dst = (u64*)sW;
        constexpr int N = (int)(sizeof(g_W) / sizeof(u64));   // 384
        for (int i = threadIdx.x; i < N; i += 256) dst[i] = src[i];
    }
    __syncthreads();

    const int gid = blockIdx.x * 256 + threadIdx.x;
    const int e = gid >> 3;        // batch element
    const int j = gid & 7;         // hidden unit owned by this thread

    // init: vald[i] = h0[e][j^i] duplicated; cc = c0[e][j]
    u64 vald[H];
#pragma unroll
    for (int i = 0; i < H; i++) {
        float v = h0[(size_t)e * H + (j ^ i)];
        vald[i] = pack2(v, v);
    }
    float cc = c0[(size_t)e * H + j];

    // Phase 1: observation scan
    lstm_scan<T_OBS>(obs, e, j, &sW[0][j][0][0], vald, cc);

    {   // c_out: out[j*B + e] = h[e][j]  (own value = lo of vald[0])
        float lo, hi; unpack2(vald[0], lo, hi);
        out[(size_t)j * BATCH + e] = lo;
    }

    // Phase 2: h carries over (vald persists), cell state reset to c0_pre
    cc = c0p[(size_t)e * H + j];
    lstm_scan<T_PRE>(pre, e, j, &sW[1][j][0][0], vald, cc);

    {
        float lo, hi; unpack2(vald[0], lo, hi);
        out[(size_t)(H + j) * BATCH + e] = lo;
    }
}

extern "C" void kernel_launch(void* const* d_in, const int* in_sizes, int n_in,
                              void* d_out, int out_size) {
    const float* obs  = (const float*)d_in[0];
    const float* pre  = (const float*)d_in[1];
    const float* h0   = (const float*)d_in[2];
    const float* c0   = (const float*)d_in[3];
    const float* c0p  = (const float*)d_in[4];

    prep_kernel<<<1, dim3(32, 2)>>>(
        (const float*)d_in[5],  (const float*)d_in[6],
        (const float*)d_in[7],  (const float*)d_in[8],
        (const float*)d_in[9],  (const float*)d_in[10],
        (const float*)d_in[11], (const float*)d_in[12],
        (const float*)d_in[13], (const float*)d_in[14]);

    // 8 threads per batch element
    lstm_kernel<<<(BATCH * 8) / 256, 256>>>(obs, pre, h0, c0, c0p, (float*)d_out);
}

// round 7
// speedup vs baseline: 1.1890x; 1.1890x over previous
#include <cuda_runtime.h>

#define T_OBS 8
#define T_PRE 12
#define BATCH 524288
#define INP 2
#define H 8
#define EMB 16

typedef unsigned long long u64;

// ---------------- packed f32x2 + fast activation helpers (sm_103a) ----------------
__device__ __forceinline__ u64 fma2(u64 a, u64 b, u64 c) {
    u64 d; asm("fma.rn.f32x2 %0, %1, %2, %3;" : "=l"(d) : "l"(a), "l"(b), "l"(c)); return d;
}
__device__ __forceinline__ u64 pack2(float lo, float hi) {
    u64 d; asm("mov.b64 %0, {%1, %2};" : "=l"(d) : "f"(lo), "f"(hi)); return d;
}
__device__ __forceinline__ void unpack2(u64 v, float& lo, float& hi) {
    asm("mov.b64 {%0, %1}, %2;" : "=f"(lo), "=f"(hi) : "l"(v));
}
__device__ __forceinline__ float tanh_ap(float x) {
    float y; asm("tanh.approx.f32 %0, %1;" : "=f"(y) : "f"(x)); return y;
}

// Folded, gate-paired, sigmoid-prescaled weights.
//   pair0 = gates (i, f): both lanes prescaled by 0.5  (sigmoid via 0.5+0.5*tanh)
//   pair1 = gates (g, o): lane lo (g) unscaled, lane hi (o) prescaled by 0.5
// Layout [phase][unit k][pair][12]: [0]=A0 [1]=A1 [2]=b [3..10]=whh[0..7] [11]=pad
__device__ float g_rows[2][32][11];
__device__ u64   g_W[2][H][2][12];
__constant__ u64 c_W[2][H][2][12];

__global__ void prep_kernel(const float* __restrict__ W_in, const float* __restrict__ b_in,
                            const float* __restrict__ W_ih_obs, const float* __restrict__ W_hh_obs,
                            const float* __restrict__ b_ih_obs, const float* __restrict__ b_hh_obs,
                            const float* __restrict__ W_ih_pre, const float* __restrict__ W_hh_pre,
                            const float* __restrict__ b_ih_pre, const float* __restrict__ b_hh_pre) {
    int j = threadIdx.x;   // gate row 0..31
    int p = threadIdx.y;   // phase
    const float* W_ih = p ? W_ih_pre : W_ih_obs;
    const float* W_hh = p ? W_hh_pre : W_hh_obs;
    const float* b_ih = p ? b_ih_pre : b_ih_obs;
    const float* b_hh = p ? b_hh_pre : b_hh_obs;

    // fold embedding: A = W_ih @ W_in (32x2), b_tot = W_ih@b_in + b_ih + b_hh
    float a0 = 0.f, a1 = 0.f, bb = 0.f;
#pragma unroll
    for (int e = 0; e < EMB; e++) {
        float w = W_ih[j * EMB + e];
        a0 = fmaf(w, W_in[e * INP + 0], a0);
        a1 = fmaf(w, W_in[e * INP + 1], a1);
        bb = fmaf(w, b_in[e], bb);
    }
    bb += b_ih[j] + b_hh[j];

    // sigmoid gates (i: rows 0..7, f: 8..15, o: 24..31) prescaled by 0.5
    float s = (j < 16 || j >= 24) ? 0.5f : 1.0f;
    g_rows[p][j][0] = a0 * s;
    g_rows[p][j][1] = a1 * s;
    g_rows[p][j][2] = bb * s;
#pragma unroll
    for (int m = 0; m < H; m++)
        g_rows[p][j][3 + m] = W_hh[j * H + m] * s;

    __syncthreads();

    if (j < 16) {
        int k  = j % H;       // unit
        int pr = j / H;       // pair
        int rlo = pr ? (16 + k) : k;        // pair0: i ; pair1: g
        int rhi = pr ? (24 + k) : (8 + k);  // pair0: f ; pair1: o
#pragma unroll
        for (int m = 0; m < 11; m++)
            g_W[p][k][pr][m] = pack2(g_rows[p][rlo][m], g_rows[p][rhi][m]);
        g_W[p][k][pr][11] = 0ull;
    }
}

// one gate-pair accumulation: 10 fma2, weights from the constant bank (LDCU path)
template <int P>
__device__ __forceinline__ u64 gate_pair(int k, int pr, u64 x0, u64 x1, const u64 hd[H]) {
    u64 a = fma2(c_W[P][k][pr][0], x0, c_W[P][k][pr][2]);
    a = fma2(c_W[P][k][pr][1], x1, a);
#pragma unroll
    for (int m = 0; m < H; m++)
        a = fma2(c_W[P][k][pr][3 + m], hd[m], a);
    return a;
}

template <int T, int P>
__device__ __forceinline__ void lstm_scan(const float* __restrict__ xin, int e,
                                          u64 hd[H], float c[H]) {
    // software-pipelined x load (depth 1)
    float2 xv = *(const float2*)(xin + (size_t)e * INP);
#pragma unroll 1
    for (int t = 0; t < T; t++) {
        u64 x0 = pack2(xv.x, xv.x);
        u64 x1 = pack2(xv.y, xv.y);
        if (t + 1 < T)
            xv = *(const float2*)(xin + ((size_t)(t + 1) * BATCH + e) * INP);
        u64 hn[H];
#pragma unroll 2
        for (int k = 0; k < H; k++) {
            u64 acc0 = gate_pair<P>(k, 0, x0, x1, hd);  // (i, f), prescaled
            u64 acc1 = gate_pair<P>(k, 1, x0, x1, hd);  // (g, o), o prescaled
            float gi, gf, gg, go;
            unpack2(acc0, gi, gf);
            unpack2(acc1, gg, go);
            float si = fmaf(0.5f, tanh_ap(gi), 0.5f);
            float sf = fmaf(0.5f, tanh_ap(gf), 0.5f);
            float gv = tanh_ap(gg);
            float so = fmaf(0.5f, tanh_ap(go), 0.5f);
            float cn = fmaf(sf, c[k], si * gv);
            c[k] = cn;
            float hv = so * tanh_ap(cn);
            hn[k] = pack2(hv, hv);
        }
#pragma unroll
        for (int k = 0; k < H; k++) hd[k] = hn[k];
    }
}

__global__ __launch_bounds__(256, 2) void lstm_kernel(
    const float* __restrict__ obs, const float* __restrict__ pre,
    const float* __restrict__ h0, const float* __restrict__ c0,
    const float* __restrict__ c0p, float* __restrict__ out)
{
    const int e = blockIdx.x * 256 + threadIdx.x;

    u64 hd[H];
    float c[H];
    {
        float4 a = *(const float4*)(h0 + (size_t)e * H);
        float4 b = *(const float4*)(h0 + (size_t)e * H + 4);
        hd[0] = pack2(a.x, a.x); hd[1] = pack2(a.y, a.y);
        hd[2] = pack2(a.z, a.z); hd[3] = pack2(a.w, a.w);
        hd[4] = pack2(b.x, b.x); hd[5] = pack2(b.y, b.y);
        hd[6] = pack2(b.z, b.z); hd[7] = pack2(b.w, b.w);
        a = *(const float4*)(c0 + (size_t)e * H);
        b = *(const float4*)(c0 + (size_t)e * H + 4);
        c[0]=a.x; c[1]=a.y; c[2]=a.z; c[3]=a.w; c[4]=b.x; c[5]=b.y; c[6]=b.z; c[7]=b.w;
    }

    // Phase 1: observation scan
    lstm_scan<T_OBS, 0>(obs, e, hd, c);

    // c_out: out[j*B + e] = h[j]
#pragma unroll
    for (int j = 0; j < H; j++) {
        float lo, hi; unpack2(hd[j], lo, hi);
        out[(size_t)j * BATCH + e] = lo;
    }

    // Phase 2: cell state reset to c0_pre, h carries over
    {
        float4 a = *(const float4*)(c0p + (size_t)e * H);
        float4 b = *(const float4*)(c0p + (size_t)e * H + 4);
        c[0]=a.x; c[1]=a.y; c[2]=a.z; c[3]=a.w; c[4]=b.x; c[5]=b.y; c[6]=b.z; c[7]=b.w;
    }
    lstm_scan<T_PRE, 1>(pre, e, hd, c);

#pragma unroll
    for (int j = 0; j < H; j++) {
        float lo, hi; unpack2(hd[j], lo, hi);
        out[(size_t)(H + j) * BATCH + e] = lo;
    }
}

extern "C" void kernel_launch(void* const* d_in, const int* in_sizes, int n_in,
                              void* d_out, int out_size) {
    const float* obs  = (const float*)d_in[0];
    const float* pre  = (const float*)d_in[1];
    const float* h0   = (const float*)d_in[2];
    const float* c0   = (const float*)d_in[3];
    const float* c0p  = (const float*)d_in[4];

    prep_kernel<<<1, dim3(32, 2)>>>(
        (const float*)d_in[5],  (const float*)d_in[6],
        (const float*)d_in[7],  (const float*)d_in[8],
        (const float*)d_in[9],  (const float*)d_in[10],
        (const float*)d_in[11], (const float*)d_in[12],
        (const float*)d_in[13], (const float*)d_in[14]);

    // stage folded weights into the constant bank (D2D async copy, capturable)
    void* gW_addr = nullptr;
    cudaGetSymbolAddress(&gW_addr, g_W);
    cudaMemcpyToSymbolAsync(c_W, gW_addr, sizeof(c_W), 0, cudaMemcpyDeviceToDevice, 0);

    lstm_kernel<<<BATCH / 256, 256>>>(obs, pre, h0, c0, c0p, (float*)d_out);
}

// round 8
// speedup vs baseline: 1.2718x; 1.0696x over previous
#include <cuda_runtime.h>

#define T_OBS 8
#define T_PRE 12
#define BATCH 524288
#define INP 2
#define H 8
#define EMB 16

typedef unsigned long long u64;

// ---------------- packed f32x2 + fast activation helpers (sm_103a) ----------------
__device__ __forceinline__ u64 fma2(u64 a, u64 b, u64 c) {
    u64 d; asm("fma.rn.f32x2 %0, %1, %2, %3;" : "=l"(d) : "l"(a), "l"(b), "l"(c)); return d;
}
__device__ __forceinline__ u64 pack2(float lo, float hi) {
    u64 d; asm("mov.b64 %0, {%1, %2};" : "=l"(d) : "f"(lo), "f"(hi)); return d;
}
__device__ __forceinline__ void unpack2(u64 v, float& lo, float& hi) {
    asm("mov.b64 {%0, %1}, %2;" : "=f"(lo), "=f"(hi) : "l"(v));
}
__device__ __forceinline__ float tanh_ap(float x) {
    float y; asm("tanh.approx.f32 %0, %1;" : "=f"(y) : "f"(x)); return y;
}

// Folded, gate-paired, sigmoid-prescaled weights.
//   pair0 = gates (i, f): both lanes prescaled by 0.5  (sigmoid = 0.5 + 0.5*tanh(acc))
//   pair1 = gates (g, o): lane lo (g) unscaled, lane hi (o) prescaled by 0.5
// Layout [phase][unit k][pair][6 ulonglong2]:
//   v0=(A0,A1) v1=(b,wh0) v2=(wh1,wh2) v3=(wh3,wh4) v4=(wh5,wh6) v5=(wh7,pad)
__device__ float      g_rows[2][32][11];
__device__ ulonglong2 g_W[2][H][2][6];

__global__ void prep_kernel(const float* __restrict__ W_in, const float* __restrict__ b_in,
                            const float* __restrict__ W_ih_obs, const float* __restrict__ W_hh_obs,
                            const float* __restrict__ b_ih_obs, const float* __restrict__ b_hh_obs,
                            const float* __restrict__ W_ih_pre, const float* __restrict__ W_hh_pre,
                            const float* __restrict__ b_ih_pre, const float* __restrict__ b_hh_pre) {
    int j = threadIdx.x;   // gate row 0..31
    int p = threadIdx.y;   // phase
    const float* W_ih = p ? W_ih_pre : W_ih_obs;
    const float* W_hh = p ? W_hh_pre : W_hh_obs;
    const float* b_ih = p ? b_ih_pre : b_ih_obs;
    const float* b_hh = p ? b_hh_pre : b_hh_obs;

    // fold embedding: A = W_ih @ W_in (32x2), b_tot = W_ih@b_in + b_ih + b_hh
    float a0 = 0.f, a1 = 0.f, bb = 0.f;
#pragma unroll
    for (int e = 0; e < EMB; e++) {
        float w = W_ih[j * EMB + e];
        a0 = fmaf(w, W_in[e * INP + 0], a0);
        a1 = fmaf(w, W_in[e * INP + 1], a1);
        bb = fmaf(w, b_in[e], bb);
    }
    bb += b_ih[j] + b_hh[j];

    // sigmoid gates (i: rows 0..7, f: 8..15, o: 24..31) prescaled by 0.5
    float s = (j < 16 || j >= 24) ? 0.5f : 1.0f;
    g_rows[p][j][0] = a0 * s;
    g_rows[p][j][1] = a1 * s;
    g_rows[p][j][2] = bb * s;
#pragma unroll
    for (int m = 0; m < H; m++)
        g_rows[p][j][3 + m] = W_hh[j * H + m] * s;

    __syncthreads();

    if (j < 16) {
        int k  = j % H;       // unit
        int pr = j / H;       // pair
        int rlo = pr ? (16 + k) : k;        // pair0: i ; pair1: g
        int rhi = pr ? (24 + k) : (8 + k);  // pair0: f ; pair1: o
        u64 vals[12];
#pragma unroll
        for (int m = 0; m < 11; m++)
            vals[m] = pack2(g_rows[p][rlo][m], g_rows[p][rhi][m]);
        vals[11] = 0ull;
#pragma unroll
        for (int m = 0; m < 6; m++) {
            ulonglong2 v; v.x = vals[2 * m]; v.y = vals[2 * m + 1];
            g_W[p][k][pr][m] = v;
        }
    }
}

// one gate-pair accumulation from pre-loaded weight registers: 10 fma2
__device__ __forceinline__ u64 gp(ulonglong2 v0, ulonglong2 v1, ulonglong2 v2,
                                  ulonglong2 v3, ulonglong2 v4, ulonglong2 v5,
                                  u64 x0, u64 x1, const u64 hd[H]) {
    u64 a = fma2(v0.x, x0, v1.x);
    a = fma2(v0.y, x1, a);
    a = fma2(v1.y, hd[0], a);
    a = fma2(v2.x, hd[1], a);
    a = fma2(v2.y, hd[2], a);
    a = fma2(v3.x, hd[3], a);
    a = fma2(v3.y, hd[4], a);
    a = fma2(v4.x, hd[5], a);
    a = fma2(v4.y, hd[6], a);
    a = fma2(v5.x, hd[7], a);
    return a;
}

// activations for one unit (prescaled rows): acc0=(i,f)/2, acc1=(g, o/2)
__device__ __forceinline__ float unit_act(u64 acc0, u64 acc1, float& c) {
    float gi, gf, gg, go;
    unpack2(acc0, gi, gf);
    unpack2(acc1, gg, go);
    float si = fmaf(0.5f, tanh_ap(gi), 0.5f);
    float sf = fmaf(0.5f, tanh_ap(gf), 0.5f);
    float gv = tanh_ap(gg);
    float so = fmaf(0.5f, tanh_ap(go), 0.5f);
    float cn = fmaf(sf, c, si * gv);
    c = cn;
    return so * tanh_ap(cn);
}

// Two-element scan: weights loaded once per unit per step, feeding 4 chains.
template <int T>
__device__ __forceinline__ void lstm_scan2(const float* __restrict__ xin, int e0,
                                           const ulonglong2 (*__restrict__ W)[2][6],
                                           u64 hdA[H], u64 hdB[H],
                                           float cA[H], float cB[H]) {
    // depth-1 prefetch; one float4 covers both elements' (x0, x1)
    float4 xv = *(const float4*)(xin + (size_t)e0 * INP);
#pragma unroll 1
    for (int t = 0; t < T; t++) {
        u64 xA0 = pack2(xv.x, xv.x), xA1 = pack2(xv.y, xv.y);
        u64 xB0 = pack2(xv.z, xv.z), xB1 = pack2(xv.w, xv.w);
        if (t + 1 < T)
            xv = *(const float4*)(xin + ((size_t)(t + 1) * BATCH + e0) * INP);

        float hnA[H], hnB[H];
#pragma unroll
        for (int k = 0; k < H; k++) {
            const ulonglong2* W0 = W[k][0];
            const ulonglong2* W1 = W[k][1];
            ulonglong2 p00 = W0[0], p01 = W0[1], p02 = W0[2];
            ulonglong2 p03 = W0[3], p04 = W0[4], p05 = W0[5];
            u64 aA0 = gp(p00, p01, p02, p03, p04, p05, xA0, xA1, hdA);
            u64 aB0 = gp(p00, p01, p02, p03, p04, p05, xB0, xB1, hdB);
            ulonglong2 p10 = W1[0], p11 = W1[1], p12 = W1[2];
            ulonglong2 p13 = W1[3], p14 = W1[4], p15 = W1[5];
            u64 aA1 = gp(p10, p11, p12, p13, p14, p15, xA0, xA1, hdA);
            u64 aB1 = gp(p10, p11, p12, p13, p14, p15, xB0, xB1, hdB);
            hnA[k] = unit_act(aA0, aA1, cA[k]);
            hnB[k] = unit_act(aB0, aB1, cB[k]);
            // pin this unit's LDS into its own scheduling region (stop front-batching)
            asm volatile("" ::: "memory");
        }
#pragma unroll
        for (int k = 0; k < H; k++) {
            hdA[k] = pack2(hnA[k], hnA[k]);
            hdB[k] = pack2(hnB[k], hnB[k]);
        }
    }
}

__global__ __launch_bounds__(256, 2) void lstm_kernel(
    const float* __restrict__ obs, const float* __restrict__ pre,
    const float* __restrict__ h0, const float* __restrict__ c0,
    const float* __restrict__ c0p, float* __restrict__ out)
{
    __shared__ ulonglong2 sW[2][H][2][6];
    {
        const u64* src = (const u64*)g_W;
        u64* dst = (u64*)sW;
        constexpr int N = (int)(sizeof(g_W) / sizeof(u64));
        for (int i = threadIdx.x; i < N; i += 256) dst[i] = src[i];
    }
    __syncthreads();

    const int gid = blockIdx.x * 256 + threadIdx.x;
    const int e0 = gid * 2;   // elements e0, e0+1

    u64 hdA[H], hdB[H];
    float cA[H], cB[H];
    {
        const float4* hp = (const float4*)(h0 + (size_t)e0 * H);
        float4 a = hp[0], b = hp[1], d = hp[2], f = hp[3];
        hdA[0]=pack2(a.x,a.x); hdA[1]=pack2(a.y,a.y); hdA[2]=pack2(a.z,a.z); hdA[3]=pack2(a.w,a.w);
        hdA[4]=pack2(b.x,b.x); hdA[5]=pack2(b.y,b.y); hdA[6]=pack2(b.z,b.z); hdA[7]=pack2(b.w,b.w);
        hdB[0]=pack2(d.x,d.x); hdB[1]=pack2(d.y,d.y); hdB[2]=pack2(d.z,d.z); hdB[3]=pack2(d.w,d.w);
        hdB[4]=pack2(f.x,f.x); hdB[5]=pack2(f.y,f.y); hdB[6]=pack2(f.z,f.z); hdB[7]=pack2(f.w,f.w);
        const float4* cp = (const float4*)(c0 + (size_t)e0 * H);
        a = cp[0]; b = cp[1]; d = cp[2]; f = cp[3];
        cA[0]=a.x; cA[1]=a.y; cA[2]=a.z; cA[3]=a.w; cA[4]=b.x; cA[5]=b.y; cA[6]=b.z; cA[7]=b.w;
        cB[0]=d.x; cB[1]=d.y; cB[2]=d.z; cB[3]=d.w; cB[4]=f.x; cB[5]=f.y; cB[6]=f.z; cB[7]=f.w;
    }

    // Phase 1: observation scan
    lstm_scan2<T_OBS>(obs, e0, sW[0], hdA, hdB, cA, cB);

    // c_out: out[j*B + e] ; pair (e0, e0+1) = one 8B store
#pragma unroll
    for (int j = 0; j < H; j++) {
        float la, ha, lb, hb;
        unpack2(hdA[j], la, ha);
        unpack2(hdB[j], lb, hb);
        *(u64*)(out + (size_t)j * BATCH + e0) = pack2(la, lb);
    }

    // Phase 2: cell state reset to c0_pre, h carries over
    {
        const float4* cp = (const float4*)(c0p + (size_t)e0 * H);
        float4 a = cp[0], b = cp[1], d = cp[2], f = cp[3];
        cA[0]=a.x; cA[1]=a.y; cA[2]=a.z; cA[3]=a.w; cA[4]=b.x; cA[5]=b.y; cA[6]=b.z; cA[7]=b.w;
        cB[0]=d.x; cB[1]=d.y; cB[2]=d.z; cB[3]=d.w; cB[4]=f.x; cB[5]=f.y; cB[6]=f.z; cB[7]=f.w;
    }
    lstm_scan2<T_PRE>(pre, e0, sW[1], hdA, hdB, cA, cB);

#pragma unroll
    for (int j = 0; j < H; j++) {
        float la, ha, lb, hb;
        unpack2(hdA[j], la, ha);
        unpack2(hdB[j], lb, hb);
        *(u64*)(out + (size_t)(H + j) * BATCH + e0) = pack2(la, lb);
    }
}

extern "C" void kernel_launch(void* const* d_in, const int* in_sizes, int n_in,
                              void* d_out, int out_size) {
    const float* obs  = (const float*)d_in[0];
    const float* pre  = (const float*)d_in[1];
    const float* h0   = (const float*)d_in[2];
    const float* c0   = (const float*)d_in[3];
    const float* c0p  = (const float*)d_in[4];

    prep_kernel<<<1, dim3(32, 2)>>>(
        (const float*)d_in[5],  (const float*)d_in[6],
        (const float*)d_in[7],  (const float*)d_in[8],
        (const float*)d_in[9],  (const float*)d_in[10],
        (const float*)d_in[11], (const float*)d_in[12],
        (const float*)d_in[13], (const float*)d_in[14]);

    // two elements per thread
    lstm_kernel<<<(BATCH / 2) / 256, 256>>>(obs, pre, h0, c0, c0p, (float*)d_out);
}

// round 9
// speedup vs baseline: 1.8515x; 1.4558x over previous
#include <cuda_runtime.h>

#define T_OBS 8
#define T_PRE 12
#define BATCH 524288
#define INP 2
#define H 8
#define EMB 16

typedef unsigned long long u64;

// ---------------- packed f32x2 + fast activation helpers (sm_103a) ----------------
__device__ __forceinline__ u64 fma2(u64 a, u64 b, u64 c) {
    u64 d; asm("fma.rn.f32x2 %0, %1, %2, %3;" : "=l"(d) : "l"(a), "l"(b), "l"(c)); return d;
}
__device__ __forceinline__ u64 pack2(float lo, float hi) {
    u64 d; asm("mov.b64 %0, {%1, %2};" : "=l"(d) : "f"(lo), "f"(hi)); return d;
}
__device__ __forceinline__ void unpack2(u64 v, float& lo, float& hi) {
    asm("mov.b64 {%0, %1}, %2;" : "=f"(lo), "=f"(hi) : "l"(v));
}
__device__ __forceinline__ float tanh_ap(float x) {
    float y; asm("tanh.approx.f32 %0, %1;" : "=f"(y) : "f"(x)); return y;
}

// Folded, gate-paired, sigmoid-prescaled weights.
//   pair0 = gates (i, f): both lanes prescaled by 0.5  (sigmoid = 0.5 + 0.5*tanh(acc))
//   pair1 = gates (g, o): lane lo (g) unscaled, lane hi (o) prescaled by 0.5
// Layout [phase][unit k][pair][6 ulonglong2]:
//   v0=(A0,A1) v1=(b,wh0) v2=(wh1,wh2) v3=(wh3,wh4) v4=(wh5,wh6) v5=(wh7,pad)
__device__ float      g_rows[2][32][11];
__device__ ulonglong2 g_W[2][H][2][6];

__global__ void prep_kernel(const float* __restrict__ W_in, const float* __restrict__ b_in,
                            const float* __restrict__ W_ih_obs, const float* __restrict__ W_hh_obs,
                            const float* __restrict__ b_ih_obs, const float* __restrict__ b_hh_obs,
                            const float* __restrict__ W_ih_pre, const float* __restrict__ W_hh_pre,
                            const float* __restrict__ b_ih_pre, const float* __restrict__ b_hh_pre) {
    int j = threadIdx.x;   // gate row 0..31
    int p = threadIdx.y;   // phase
    const float* W_ih = p ? W_ih_pre : W_ih_obs;
    const float* W_hh = p ? W_hh_pre : W_hh_obs;
    const float* b_ih = p ? b_ih_pre : b_ih_obs;
    const float* b_hh = p ? b_hh_pre : b_hh_obs;

    // fold embedding: A = W_ih @ W_in (32x2), b_tot = W_ih@b_in + b_ih + b_hh
    float a0 = 0.f, a1 = 0.f, bb = 0.f;
#pragma unroll
    for (int e = 0; e < EMB; e++) {
        float w = W_ih[j * EMB + e];
        a0 = fmaf(w, W_in[e * INP + 0], a0);
        a1 = fmaf(w, W_in[e * INP + 1], a1);
        bb = fmaf(w, b_in[e], bb);
    }
    bb += b_ih[j] + b_hh[j];

    // sigmoid gates (i: rows 0..7, f: 8..15, o: 24..31) prescaled by 0.5
    float s = (j < 16 || j >= 24) ? 0.5f : 1.0f;
    g_rows[p][j][0] = a0 * s;
    g_rows[p][j][1] = a1 * s;
    g_rows[p][j][2] = bb * s;
#pragma unroll
    for (int m = 0; m < H; m++)
        g_rows[p][j][3 + m] = W_hh[j * H + m] * s;

    __syncthreads();

    if (j < 16) {
        int k  = j % H;       // unit
        int pr = j / H;       // pair
        int rlo = pr ? (16 + k) : k;        // pair0: i ; pair1: g
        int rhi = pr ? (24 + k) : (8 + k);  // pair0: f ; pair1: o
        u64 vals[12];
#pragma unroll
        for (int m = 0; m < 11; m++)
            vals[m] = pack2(g_rows[p][rlo][m], g_rows[p][rhi][m]);
        vals[11] = 0ull;
#pragma unroll
        for (int m = 0; m < 6; m++) {
            ulonglong2 v; v.x = vals[2 * m]; v.y = vals[2 * m + 1];
            g_W[p][k][pr][m] = v;
        }
    }
}

// one gate-pair accumulation from freshly-loaded weight registers: 10 fma2
__device__ __forceinline__ u64 gp(const ulonglong2* __restrict__ Wr,
                                  u64 x0, u64 x1, const u64 hd[H]) {
    ulonglong2 v0 = Wr[0];
    ulonglong2 v1 = Wr[1];
    u64 a = fma2(v0.x, x0, v1.x);
    a = fma2(v0.y, x1, a);
    a = fma2(v1.y, hd[0], a);
    ulonglong2 v2 = Wr[2];
    a = fma2(v2.x, hd[1], a);
    a = fma2(v2.y, hd[2], a);
    ulonglong2 v3 = Wr[3];
    a = fma2(v3.x, hd[3], a);
    a = fma2(v3.y, hd[4], a);
    ulonglong2 v4 = Wr[4];
    a = fma2(v4.x, hd[5], a);
    a = fma2(v4.y, hd[6], a);
    ulonglong2 v5 = Wr[5];
    a = fma2(v5.x, hd[7], a);
    return a;
}

// activations for one unit (prescaled rows): acc0=(i/2, f/2), acc1=(g, o/2)
__device__ __forceinline__ float unit_act(u64 acc0, u64 acc1, float& c) {
    float gi, gf, gg, go;
    unpack2(acc0, gi, gf);
    unpack2(acc1, gg, go);
    float si = fmaf(0.5f, tanh_ap(gi), 0.5f);
    float sf = fmaf(0.5f, tanh_ap(gf), 0.5f);
    float gv = tanh_ap(gg);
    float so = fmaf(0.5f, tanh_ap(go), 0.5f);
    float cn = fmaf(sf, c, si * gv);
    c = cn;
    return so * tanh_ap(cn);
}

template <int T>
__device__ __forceinline__ void lstm_scan(const float* __restrict__ xin, int e,
                                          const ulonglong2 (*__restrict__ W)[2][6],
                                          u64 hd[H], float c[H]) {
    // depth-1 software-pipelined x load
    float2 xv = *(const float2*)(xin + (size_t)e * INP);
#pragma unroll 1
    for (int t = 0; t < T; t++) {
        u64 x0 = pack2(xv.x, xv.x);
        u64 x1 = pack2(xv.y, xv.y);
        if (t + 1 < T)
            xv = *(const float2*)(xin + ((size_t)(t + 1) * BATCH + e) * INP);

        float hn[H];
        // fully unrolled: all state statically indexed (registers, zero LDL/STL)
#pragma unroll
        for (int k = 0; k < H; k++) {
            u64 acc0 = gp(W[k][0], x0, x1, hd);  // (i, f), prescaled
            u64 acc1 = gp(W[k][1], x0, x1, hd);  // (g, o), o prescaled
            hn[k] = unit_act(acc0, acc1, c[k]);
            // pin this unit's 12 LDS.128 into its own region (stop front-batching)
            asm volatile("" ::: "memory");
        }
#pragma unroll
        for (int k = 0; k < H; k++) hd[k] = pack2(hn[k], hn[k]);
    }
}

__global__ __launch_bounds__(256, 2) void lstm_kernel(
    const float* __restrict__ obs, const float* __restrict__ pre,
    const float* __restrict__ h0, const float* __restrict__ c0,
    const float* __restrict__ c0p, float* __restrict__ out)
{
    __shared__ ulonglong2 sW[2][H][2][6];
    {
        const u64* src = (const u64*)g_W;
        u64* dst = (u64*)sW;
        constexpr int N = (int)(sizeof(g_W) / sizeof(u64));
        for (int i = threadIdx.x; i < N; i += 256) dst[i] = src[i];
    }
    __syncthreads();

    const int e = blockIdx.x * 256 + threadIdx.x;

    u64 hd[H];
    float c[H];
    {
        float4 a = *(const float4*)(h0 + (size_t)e * H);
        float4 b = *(const float4*)(h0 + (size_t)e * H + 4);
        hd[0] = pack2(a.x, a.x); hd[1] = pack2(a.y, a.y);
        hd[2] = pack2(a.z, a.z); hd[3] = pack2(a.w, a.w);
        hd[4] = pack2(b.x, b.x); hd[5] = pack2(b.y, b.y);
        hd[6] = pack2(b.z, b.z); hd[7] = pack2(b.w, b.w);
        a = *(const float4*)(c0 + (size_t)e * H);
        b = *(const float4*)(c0 + (size_t)e * H + 4);
        c[0]=a.x; c[1]=a.y; c[2]=a.z; c[3]=a.w; c[4]=b.x; c[5]=b.y; c[6]=b.z; c[7]=b.w;
    }

    // Phase 1: observation scan
    lstm_scan<T_OBS>(obs, e, sW[0], hd, c);

    // c_out: out[j*B + e] = h[j]
#pragma unroll
    for (int j = 0; j < H; j++) {
        float lo, hi; unpack2(hd[j], lo, hi);
        out[(size_t)j * BATCH + e] = lo;
    }

    // Phase 2: cell state reset to c0_pre, h carries over
    {
        float4 a = *(const float4*)(c0p + (size_t)e * H);
        float4 b = *(const float4*)(c0p + (size_t)e * H + 4);
        c[0]=a.x; c[1]=a.y; c[2]=a.z; c[3]=a.w; c[4]=b.x; c[5]=b.y; c[6]=b.z; c[7]=b.w;
    }
    lstm_scan<T_PRE>(pre, e, sW[1], hd, c);

#pragma unroll
    for (int j = 0; j < H; j++) {
        float lo, hi; unpack2(hd[j], lo, hi);
        out[(size_t)(H + j) * BATCH + e] = lo;
    }
}

extern "C" void kernel_launch(void* const* d_in, const int* in_sizes, int n_in,
                              void* d_out, int out_size) {
    const float* obs  = (const float*)d_in[0];
    const float* pre  = (const float*)d_in[1];
    const float* h0   = (const float*)d_in[2];
    const float* c0   = (const float*)d_in[3];
    const float* c0p  = (const float*)d_in[4];

    prep_kernel<<<1, dim3(32, 2)>>>(
        (const float*)d_in[5],  (const float*)d_in[6],
        (const float*)d_in[7],  (const float*)d_in[8],
        (const float*)d_in[9],  (const float*)d_in[10],
        (const float*)d_in[11], (const float*)d_in[12],
        (const float*)d_in[13], (const float*)d_in[14]);

    lstm_kernel<<<BATCH / 256, 256>>>(obs, pre, h0, c0, c0p, (float*)d_out);
}